// round 10
// baseline (speedup 1.0000x reference)
#include <cuda_runtime.h>
#include <cuda_fp16.h>
#include <math.h>

#define BATCH 16
#define IMH 768
#define IMW 768
#define TILE 32
#define R3 9
#define LOAD 50              // TILE + 18
#define XSTR 53              // half2 raw tile stride (elements)
#define USTR 51              // half u tile stride
#define HSTR 33              // blurred plane stride
#define H1ROWS 38
#define NBINS 512
#define NWORDS (NBINS/2)
#define NTHREADS 256
#define NACC 15
#define GRID_BLOCKS ((IMW/TILE)*(IMH/TILE)*BATCH)   // 9216

// byte offsets in dynamic smem
#define OFF_XY   0                               // half2[50*53]  = 10600 B
#define OFF_H3   (OFF_XY + LOAD*XSTR*4)          // half2[50*33]  =  6600 B
#define OFF_H3U  (OFF_H3 + LOAD*HSTR*4)          // half [50*33]  =  3300 B
#define OFF_U    (OFF_H3U + LOAD*HSTR*2)         // half [50*51]  =  5100 B
#define OFF_H1   (OFF_U + LOAD*USTR*2)           // half2[38*33]  =  5016 B
#define OFF_HIST (OFF_H1 + H1ROWS*HSTR*4)        // u32 [512]     =  2048 B
#define SMEM_BYTES (OFF_HIST + 2*NWORDS*4)       // 32664 B

#define NH3 (LOAD*8)                 // 400 G3-h work items
#define NH1 (H1ROWS*8)               // 304 G1-h work items

__device__ constexpr float G3W[19] = {
    0.00147944f, 0.00380430f, 0.00875341f, 0.01802349f, 0.03320783f,
    0.05475024f, 0.08077522f, 0.10663890f, 0.12597909f, 0.13317587f,
    0.12597909f, 0.10663890f, 0.08077522f, 0.05475024f, 0.03320783f,
    0.01802349f, 0.00875341f, 0.00380430f, 0.00147944f };
__device__ constexpr float G1W[7] = {
    0.00443305f, 0.05400558f, 0.24203623f, 0.39905027f,
    0.24203623f, 0.05400558f, 0.00443305f };

__device__ double       g_acc[NACC];
__device__ unsigned int g_histp[2*NWORDS];
__device__ unsigned int g_ticket;

__global__ __launch_bounds__(NTHREADS, 4)
void main_kernel(const float* __restrict__ yp_g,
                 const float* __restrict__ np_g,
                 const float* __restrict__ xi_g,
                 const float* __restrict__ xm_g,
                 const float* __restrict__ wt_g,
                 const float* __restrict__ ns_g,
                 float* __restrict__ out)
{
    extern __shared__ char smem_raw[];
    __half2* s_xy  = (__half2*)(smem_raw + OFF_XY);
    __half2* s_h3  = (__half2*)(smem_raw + OFF_H3);
    __half*  s_h3u = (__half*)(smem_raw + OFF_H3U);
    __half*  s_u   = (__half*)(smem_raw + OFF_U);
    __half2* s_h1  = (__half2*)(smem_raw + OFF_H1);
    unsigned int* s_hist = (unsigned int*)(smem_raw + OFF_HIST);

    __shared__ float s_part[NACC][8];
    __shared__ unsigned int s_wtot[8];
    __shared__ double s_q[4];
    __shared__ bool s_last;

    const int tid = threadIdx.x;
    for (int i = tid; i < 2*NWORDS; i += NTHREADS) s_hist[i] = 0u;

    __half2 w3[19], w1[7];
    __half  w3s[19];
    #pragma unroll
    for (int t = 0; t < 19; t++) { w3[t] = __float2half2_rn(G3W[t]); w3s[t] = __float2half_rn(G3W[t]); }
    #pragma unroll
    for (int t = 0; t < 7; t++)  { w1[t] = __float2half2_rn(G1W[t]); }

    const int oy = blockIdx.y * TILE;
    const int ox = blockIdx.x * TILE;
    const int img = blockIdx.z * (IMH * IMW);

    // ---- load raw tiles: (xi,yp) packed half2, u = yp-0.3xi-0.7xm as half ----
    for (int i = tid; i < LOAD*LOAD; i += NTHREADS) {
        int r = i / LOAD, c = i - r * LOAD;
        int gy = oy + r - R3, gx = ox + c - R3;
        bool in = ((unsigned)gy < IMH) & ((unsigned)gx < IMW);
        float vx = 0.f, vy = 0.f, vm = 0.f;
        if (in) {
            int g = img + gy * IMW + gx;
            vx = xi_g[g]; vy = yp_g[g]; vm = xm_g[g];
        }
        s_xy[r*XSTR + c] = __floats2half2_rn(vx, vy);
        s_u [r*USTR + c] = __float2half_rn(fmaf(-0.7f, vm, fmaf(-0.3f, vx, vy)));
    }
    __syncthreads();

    // ---- merged horizontal passes (G3 on xy+u, then G1 on xy), one barrier ----
    for (int i = tid; i < NH3 + NH1; i += NTHREADS) {
        if (i < NH3) {
            int r = i >> 3, c4 = (i & 7) << 2;
            int bx = r*XSTR + c4, bu = r*USTR + c4;
            __half2 a0 = __float2half2_rn(0.f), a1 = a0, a2 = a0, a3 = a0;
            __half  m0 = __float2half_rn(0.f), m1 = m0, m2 = m0, m3 = m0;
            #pragma unroll
            for (int t = 0; t < 22; t++) {
                __half2 v = s_xy[bx + t];
                __half vu = s_u[bu + t];
                if (t <= 18)           { a0 = __hfma2(v, w3[t  ], a0); m0 = __hfma(vu, w3s[t  ], m0); }
                if (t >= 1 && t <= 19) { a1 = __hfma2(v, w3[t-1], a1); m1 = __hfma(vu, w3s[t-1], m1); }
                if (t >= 2 && t <= 20) { a2 = __hfma2(v, w3[t-2], a2); m2 = __hfma(vu, w3s[t-2], m2); }
                if (t >= 3)            { a3 = __hfma2(v, w3[t-3], a3); m3 = __hfma(vu, w3s[t-3], m3); }
            }
            int o = r*HSTR + c4;
            s_h3[o]=a0; s_h3[o+1]=a1; s_h3[o+2]=a2; s_h3[o+3]=a3;
            s_h3u[o]=m0; s_h3u[o+1]=m1; s_h3u[o+2]=m2; s_h3u[o+3]=m3;
        } else {
            int j = i - NH3;
            int r = j >> 3, c4 = (j & 7) << 2;
            int bx = (r + 6)*XSTR + c4 + 6;
            __half2 a0 = __float2half2_rn(0.f), a1 = a0, a2 = a0, a3 = a0;
            #pragma unroll
            for (int t = 0; t < 10; t++) {
                __half2 v = s_xy[bx + t];
                if (t <= 6)           { a0 = __hfma2(v, w1[t  ], a0); }
                if (t >= 1 && t <= 7) { a1 = __hfma2(v, w1[t-1], a1); }
                if (t >= 2 && t <= 8) { a2 = __hfma2(v, w1[t-2], a2); }
                if (t >= 3)           { a3 = __hfma2(v, w1[t-3], a3); }
            }
            int o = r*HSTR + c4;
            s_h1[o]=a0; s_h1[o+1]=a1; s_h1[o+2]=a2; s_h1[o+3]=a3;
        }
    }
    __syncthreads();

    // ---- per-pixel phase: thread owns column c, rows r0..r0+3 ----
    const int c  = tid & 31;
    const int r0 = (tid >> 5) << 2;

    __half2 LIP[4]; __half LU[4];
    #pragma unroll
    for (int j = 0; j < 4; j++) { LIP[j] = __float2half2_rn(0.f); LU[j] = __float2half_rn(0.f); }
    #pragma unroll
    for (int t = 0; t < 22; t++) {
        int idx = (r0 + t)*HSTR + c;
        __half2 v = s_h3[idx];
        __half vu = s_h3u[idx];
        if (t <= 18)           { LIP[0]=__hfma2(v,w3[t  ],LIP[0]); LU[0]=__hfma(vu,w3s[t  ],LU[0]); }
        if (t >= 1 && t <= 19) { LIP[1]=__hfma2(v,w3[t-1],LIP[1]); LU[1]=__hfma(vu,w3s[t-1],LU[1]); }
        if (t >= 2 && t <= 20) { LIP[2]=__hfma2(v,w3[t-2],LIP[2]); LU[2]=__hfma(vu,w3s[t-2],LU[2]); }
        if (t >= 3)            { LIP[3]=__hfma2(v,w3[t-3],LIP[3]); LU[3]=__hfma(vu,w3s[t-3],LU[3]); }
    }
    __half2 G1P[4];
    #pragma unroll
    for (int j = 0; j < 4; j++) G1P[j] = __float2half2_rn(0.f);
    #pragma unroll
    for (int t = 0; t < 10; t++) {
        __half2 v = s_h1[(r0 + t)*HSTR + c];
        if (t <= 6)           { G1P[0]=__hfma2(v,w1[t  ],G1P[0]); }
        if (t >= 1 && t <= 7) { G1P[1]=__hfma2(v,w1[t-1],G1P[1]); }
        if (t >= 2 && t <= 8) { G1P[2]=__hfma2(v,w1[t-2],G1P[2]); }
        if (t >= 3)           { G1P[3]=__hfma2(v,w1[t-3],G1P[3]); }
    }

    float p_rc=0,p_nb=0,p_sxi=0,p_syp=0,p_ex=0,p_ey=0,p_ntex=0,p_stex=0;
    float p_nf=0,p_nfb=0,p_lf=0,p_mid=0,p_hf=0,p_syn=0,p_ic=0;
    const __half2 TWO2 = __float2half2_rn(2.0f);
    const __half2 NEG42 = __float2half2_rn(-4.0f);

    int rb = (r0 + R3 - 1)*XSTR + (c + R3 - 1);
    __half2 v00=s_xy[rb],      v01=s_xy[rb+1],      v02=s_xy[rb+2];
    __half2 v10=s_xy[rb+XSTR], v11=s_xy[rb+XSTR+1], v12=s_xy[rb+XSTR+2];

    #pragma unroll
    for (int j = 0; j < 4; j++) {
        int rbn = rb + (j+2)*XSTR;
        __half2 v20=s_xy[rbn], v21=s_xy[rbn+1], v22=s_xy[rbn+2];

        __half2 gx2 = __hfma2(__hsub2(v12,v10), TWO2, __hadd2(__hsub2(v02,v00), __hsub2(v22,v20)));
        __half2 gy2 = __hfma2(__hsub2(v21,v01), TWO2, __hadd2(__hsub2(v20,v00), __hsub2(v22,v02)));
        __half2 lp2 = __hfma2(v11, NEG42, __hadd2(__hadd2(v01,v10), __hadd2(v12,v21)));

        float gxi = __low2float(gx2), gxp = __high2float(gx2);
        float gyi = __low2float(gy2), gyp = __high2float(gy2);
        float lap_i = __low2float(lp2), lap_p = __high2float(lp2);

        // exact center values from global (L1 hits; removes half error from
        // rc / body mask / histogram / hu means)
        int g = img + (oy + r0 + j)*IMW + (ox + c);
        float xi   = xi_g[g];
        float yp   = yp_g[g];
        float wv   = wt_g[g];
        float nprd = np_g[g];
        float nsyn = ns_g[g];

        p_rc += fabsf(yp*wv - xi*wv);

        bool body = (xi > 0.15f) & (xi < 0.85f);
        if (body) {
            p_nb += 1.f; p_sxi += xi; p_syp += yp;
            int b1 = min(max((int)(yp * (float)NBINS), 0), NBINS-1);
            atomicAdd(&s_hist[b1 >> 1], 1u << ((b1 & 1) * 16));
            int b2 = min(max((int)(xi * (float)NBINS), 0), NBINS-1);
            atomicAdd(&s_hist[NWORDS + (b2 >> 1)], 1u << ((b2 & 1) * 16));
        }

        p_ex += fabsf(gxp - gxi);
        p_ey += fabsf(gyp - gyi);

        float gmi = sqrtf(fmaf(gxi,gxi, gyi*gyi) + 1e-8f);
        float gmp = sqrtf(fmaf(gxp,gxp, gyp*gyp) + 1e-8f);

        bool tex = (gmi > 0.03f) & (gmi < 0.5f);
        if (tex) { p_ntex += 1.f; p_stex += fabsf(gmp - gmi); }

        bool flat = (gmi < 0.03f);
        if (flat) {
            p_nf += 1.f;
            p_hf += fabsf(fabsf(lap_p) - 0.3f*fabsf(lap_i));
            p_ic += fmaxf(gmp - 2.0f*gmi, 0.f);
            if (body) {
                p_nfb += 1.f;
                p_lf  += fabsf(__half2float(LU[j]));
                float low_i = __low2float(LIP[j]), low_p = __high2float(LIP[j]);
                float g1i   = __low2float(G1P[j]), g1p   = __high2float(G1P[j]);
                p_mid += fabsf(fabsf(g1p - low_p) - 0.3f*fabsf(g1i - low_i));
                p_syn += fabsf(nprd - nsyn);
            }
        }

        v00=v10; v01=v11; v02=v12; v10=v20; v11=v21; v12=v22;
    }

    // ---- block reduction of 15 partials ----
    float vals[NACC] = {p_rc, p_nb, p_sxi, p_syp, p_ex, p_ey, p_ntex, p_stex,
                        p_nf, p_nfb, p_lf, p_mid, p_hf, p_syn, p_ic};
    int lane = tid & 31, warp = tid >> 5;
    #pragma unroll
    for (int q = 0; q < NACC; q++) {
        float v = vals[q];
        #pragma unroll
        for (int o = 16; o > 0; o >>= 1) v += __shfl_down_sync(0xffffffffu, v, o);
        if (lane == 0) s_part[q][warp] = v;
    }
    __syncthreads();
    if (tid < NACC) {
        float s = 0.f;
        #pragma unroll
        for (int w = 0; w < 8; w++) s += s_part[tid][w];
        atomicAdd(&g_acc[tid], (double)s);
    }
    for (int i = tid; i < 2*NWORDS; i += NTHREADS) {
        unsigned int h = s_hist[i];
        if (h) atomicAdd(&g_histp[i], h);
    }

    // ---- last-block finalize ----
    __syncthreads();
    if (tid == 0) {
        __threadfence();
        unsigned t = atomicAdd(&g_ticket, 1u);
        s_last = (t == GRID_BLOCKS - 1);
    }
    __syncthreads();
    if (!s_last) return;
    __threadfence();

    unsigned int* s_cum = s_hist;
    const double nb = g_acc[1];

    for (int h = 0; h < 2; h++) {
        unsigned int w0 = g_histp[h*NWORDS + tid];
        unsigned int lo = w0 & 0xffffu, hi = w0 >> 16;
        unsigned int run = lo + hi;
        unsigned int v = run;
        #pragma unroll
        for (int o = 1; o < 32; o <<= 1) {
            unsigned int u = __shfl_up_sync(0xffffffffu, v, o);
            if (lane >= o) v += u;
        }
        __syncthreads();
        if (lane == 31) s_wtot[warp] = v;
        __syncthreads();
        unsigned int woff = 0;
        for (int w = 0; w < warp; w++) woff += s_wtot[w];
        unsigned int off = woff + v - run;
        s_cum[2*tid]   = off + lo;
        s_cum[2*tid+1] = off + run;
        __syncthreads();
        if (tid < 2) {
            double q = (tid == 0) ? 0.25 : 0.75;
            double pos = q * (nb - 1.0);
            int lo_i = 0, hi_i = NBINS - 1;
            while (lo_i < hi_i) {
                int m = (lo_i + hi_i) >> 1;
                if ((double)s_cum[m] > pos) hi_i = m; else lo_i = m + 1;
            }
            int b = lo_i;
            unsigned int cb = s_cum[b];
            unsigned int pv = b ? s_cum[b-1] : 0u;
            double cnt = (double)(cb - pv);
            double val = 0.0;
            if (cnt > 0.0) {
                double frac = (pos - (double)pv + 0.5) / cnt;
                frac = fmin(fmax(frac, 0.0), 1.0);
                val = ((double)b + frac) / (double)NBINS;
            }
            s_q[h*2 + tid] = val;
        }
        __syncthreads();
    }

    if (tid == 0) {
        const double n_all = (double)BATCH * IMH * IMW;
        double rc = g_acc[0] / n_all;
        double denb = fmax(nb, 1.0);
        double mean_in = g_acc[2] / denb;
        double mean_pr = g_acc[3] / denb;
        double dm  = mean_pr - mean_in;
        double d25 = s_q[0] - s_q[2];
        double d75 = s_q[1] - s_q[3];
        double hu  = dm*dm + 0.5*(d25*d25 + d75*d75);
        double loss_hu = (nb > 4096.0) ? hu : 0.0;
        double edge = g_acc[4]/n_all + g_acc[5]/n_all;
        double ntex = g_acc[6];
        double tex = (ntex > 100.0) ? g_acc[7]/fmax(ntex, 1.0) : 0.0;
        double nf = g_acc[8], nfb = g_acc[9];
        double lf  = (nfb > 100.0) ? g_acc[10]/fmax(nfb, 1.0) : 0.0;
        double mid = (nfb > 100.0) ? g_acc[11]/fmax(nfb, 1.0) : 0.0;
        double hf  = (nf  > 100.0) ? g_acc[12]/fmax(nf, 1.0)  : 0.0;
        double syn = (nfb > 100.0) ? g_acc[13]/fmax(nfb, 1.0) : 0.0;
        double ic  = (nf  > 100.0) ? g_acc[14]/fmax(nf, 1.0)  : 0.0;

        double total = 2.0*rc + 1.5*loss_hu + 1.0*edge + 0.8*tex
                     + 1.5*hf + 0.8*mid + 0.6*lf + 1.0*syn + 0.8*ic;
        out[0] = (float)total;
    }
    __syncthreads();

    for (int i = tid; i < 2*NWORDS; i += NTHREADS) g_histp[i] = 0u;
    if (tid < NACC) g_acc[tid] = 0.0;
    if (tid == 0) g_ticket = 0u;
}

extern "C" void kernel_launch(void* const* d_in, const int* in_sizes, int n_in,
                              void* d_out, int out_size) {
    const float* yp = (const float*)d_in[0];   // y_pred
    const float* np = (const float*)d_in[1];   // noise_pred
    const float* xi = (const float*)d_in[2];   // x_i
    // d_in[3] = x_ip1 (unused by reference)
    const float* xm = (const float*)d_in[4];   // x_mid
    const float* wt = (const float*)d_in[5];   // W
    const float* ns = (const float*)d_in[6];   // noise_synthetic
    float* out = (float*)d_out;

    cudaFuncSetAttribute(main_kernel,
                         cudaFuncAttributeMaxDynamicSharedMemorySize, SMEM_BYTES);

    dim3 grid(IMW / TILE, IMH / TILE, BATCH);
    main_kernel<<<grid, NTHREADS, SMEM_BYTES>>>(yp, np, xi, xm, wt, ns, out);
}